// round 16
// baseline (speedup 1.0000x reference)
#include <cuda_runtime.h>
#include <cuda_bf16.h>
#include <cstdint>

// Problem constants (fixed shapes)
#define BT    16384      // B*T
#define HID   512
#define NP    30
#define NU    600
#define NA    80
#define NK    10

// Scratch: transposed exp'ed params [p][bt].
__device__ float g_par[NP * BT];
// Pre-split W, transposed n-major: [n][k], n padded 30->32 with zeros.
__device__ __nv_bfloat16 g_wh[32 * HID];
__device__ __nv_bfloat16 g_wl[32 * HID];

__device__ __forceinline__ uint32_t smem_u32(const void* p) {
    return (uint32_t)__cvta_generic_to_shared(p);
}
__device__ __forceinline__ void ldsm_x4(uint32_t& r0, uint32_t& r1,
                                        uint32_t& r2, uint32_t& r3, uint32_t addr) {
    asm volatile("ldmatrix.sync.aligned.m8n8.x4.shared.b16 {%0,%1,%2,%3}, [%4];"
                 : "=r"(r0), "=r"(r1), "=r"(r2), "=r"(r3) : "r"(addr));
}
__device__ __forceinline__ void mma_bf16(float* c, const uint32_t* a,
                                         uint32_t b0, uint32_t b1) {
    asm volatile(
        "mma.sync.aligned.m16n8k16.row.col.f32.bf16.bf16.f32 "
        "{%0,%1,%2,%3}, {%4,%5,%6,%7}, {%8,%9}, {%0,%1,%2,%3};"
        : "+f"(c[0]), "+f"(c[1]), "+f"(c[2]), "+f"(c[3])
        : "r"(a[0]), "r"(a[1]), "r"(a[2]), "r"(a[3]), "r"(b0), "r"(b1));
}
__device__ __forceinline__ void cp_async16(uint32_t smem_dst, const void* gmem_src) {
    asm volatile("cp.async.ca.shared.global [%0], [%1], 16;"
                 :: "r"(smem_dst), "l"(gmem_src));
}
#define CP_COMMIT() asm volatile("cp.async.commit_group;" ::: "memory")
#define CP_WAIT2()  asm volatile("cp.async.wait_group 2;" ::: "memory")

// ---------------------------------------------------------------------------
// Kernel 0 (R10 verbatim): split W into bf16 hi/lo transposed [32][512].
// ---------------------------------------------------------------------------
__global__ __launch_bounds__(256) void k0_wsplit(const float* __restrict__ W)
{
    int idx = blockIdx.x * 256 + threadIdx.x;   // 0..16383
    int n = idx >> 9, k = idx & 511;
    float f = (n < NP) ? W[(size_t)k * NP + n] : 0.f;
    __nv_bfloat16 hi = __float2bfloat16(f);
    __nv_bfloat16 lo = __float2bfloat16(f - __bfloat162float(hi));
    g_wh[idx] = hi;
    g_wl[idx] = lo;
}

// ---------------------------------------------------------------------------
// Kernel 1 (cp.async pipelined): params = lstm @ W + bias -> exp -> g_par.
// 256 CTAs x 64 t; 128 threads (4 warps x m16 x n32). K in 16 chunks of 32.
// A staged as f32 via cp.async, 4 stages deep (wait_group 2 => ~3 chunks of
// latency cover; barriers never wait on DRAM). Convert pass: LDS f32 -> bf16
// hi/lo STS. 3-term bf16 split (Ah*Wh + Ah*Wl + Al*Wh, residual ~2^-17).
// All smem strides = 16 mod 128 bytes -> conflict-free LDS/LDSM (verified).
// ---------------------------------------------------------------------------
#define K1T    128
#define MROWS  64
#define KC     32
#define NCHC   (HID / KC)     // 16
#define STGF   36             // f32 stage row stride (144B)
#define BSTR   40             // bf16 tile row stride (80B)

#define OFF_STG  0                       // 4 x 64*36*4 = 4 x 9216 = 36864
#define STGB     9216
#define OFF_AH   36864                   // 64*40*2 = 5120
#define OFF_AL   41984                   // 5120
#define OFF_WH   47104                   // 32*40*2 = 2560
#define OFF_WL   49664                   // 2560
#define K1_SMEM  52224

__global__ __launch_bounds__(K1T) void k1_hmma(
    const float* __restrict__ lstm,
    const float* __restrict__ bias)
{
    extern __shared__ __align__(16) char buf[];
    const uint32_t sbase = smem_u32(buf);
    __nv_bfloat16* sAh = reinterpret_cast<__nv_bfloat16*>(buf + OFF_AH);
    __nv_bfloat16* sAl = reinterpret_cast<__nv_bfloat16*>(buf + OFF_AL);
    __nv_bfloat16* sWh = reinterpret_cast<__nv_bfloat16*>(buf + OFF_WH);
    __nv_bfloat16* sWl = reinterpret_cast<__nv_bfloat16*>(buf + OFF_WL);

    const int tid = threadIdx.x;
    const int wid = tid >> 5;
    const int lid = tid & 31;
    const int t0  = blockIdx.x * MROWS;
    const int m0  = wid * 16;

    // cp.async issue for one chunk: 512 float4, 4 per thread
    const int arow = tid >> 3;            // +32 for second half (j=1..3 below)
    const int ac4  = tid & 7;
    auto issue_chunk = [&](int ch) {
        uint32_t dst = sbase + OFF_STG + (uint32_t)((ch & 3) * STGB);
        const float* src = lstm + (size_t)t0 * HID + ch * KC;
        #pragma unroll
        for (int j = 0; j < 4; j++) {
            int row = arow + 16 * j;
            cp_async16(dst + (uint32_t)(row * STGF + ac4 * 4) * 4,
                       src + (size_t)row * HID + ac4 * 4);
        }
        CP_COMMIT();
    };

    // W chunk regs: per split 32n x 32k = 128 uint4; 1 per thread.
    const int wn = tid >> 2, wk8 = (tid & 3) * 8;
    uint4 wbh, wbl;
    auto ldg_w = [&](int ch) {
        wbh = *reinterpret_cast<const uint4*>(&g_wh[wn * HID + ch * KC + wk8]);
        wbl = *reinterpret_cast<const uint4*>(&g_wl[wn * HID + ch * KC + wk8]);
    };

    // prologue: stages 0..2 in flight, W chunk 0 in regs
    issue_chunk(0);
    issue_chunk(1);
    issue_chunk(2);
    ldg_w(0);

    float acc[4][4];
    #pragma unroll
    for (int n = 0; n < 4; n++)
        #pragma unroll
        for (int j = 0; j < 4; j++) acc[n][j] = 0.f;

    // ldmatrix lane addresses
    const uint32_t aoffB = (uint32_t)((m0 + (lid & 15)) * BSTR +
                                      ((lid & 16) ? 8 : 0)) * 2;
    const uint32_t aH = sbase + OFF_AH + aoffB;
    const uint32_t aL = sbase + OFF_AL + aoffB;
    const int b_n = (lid & 7) + ((lid & 16) ? 8 : 0);
    const uint32_t boffB = (uint32_t)(b_n * BSTR + ((lid & 8) ? 8 : 0)) * 2;
    const uint32_t bH = sbase + OFF_WH + boffB;
    const uint32_t bL = sbase + OFF_WL + boffB;

    #pragma unroll 1
    for (int ch = 0; ch < NCHC; ch++) {
        CP_WAIT2();            // chunk ch resident (stages ch+1, ch+2 pending)
        __syncthreads();       // prev MMA done reading bf16 tiles

        // convert: f32 stage -> bf16 hi/lo tiles; store W chunk; prefetch W
        {
            const float* stg = reinterpret_cast<const float*>(
                buf + OFF_STG + (ch & 3) * STGB);
            #pragma unroll
            for (int j = 0; j < 4; j++) {
                int row = arow + 16 * j;
                float4 v = *reinterpret_cast<const float4*>(
                    &stg[row * STGF + ac4 * 4]);
                __nv_bfloat162 h01 = __float22bfloat162_rn(make_float2(v.x, v.y));
                __nv_bfloat162 h23 = __float22bfloat162_rn(make_float2(v.z, v.w));
                float2 f01 = __bfloat1622float2(h01);
                float2 f23 = __bfloat1622float2(h23);
                __nv_bfloat162 l01 = __float22bfloat162_rn(
                    make_float2(v.x - f01.x, v.y - f01.y));
                __nv_bfloat162 l23 = __float22bfloat162_rn(
                    make_float2(v.z - f23.x, v.w - f23.y));
                *reinterpret_cast<uint2*>(&sAh[row * BSTR + ac4 * 4]) =
                    make_uint2(*reinterpret_cast<uint32_t*>(&h01),
                               *reinterpret_cast<uint32_t*>(&h23));
                *reinterpret_cast<uint2*>(&sAl[row * BSTR + ac4 * 4]) =
                    make_uint2(*reinterpret_cast<uint32_t*>(&l01),
                               *reinterpret_cast<uint32_t*>(&l23));
            }
            *reinterpret_cast<uint4*>(&sWh[wn * BSTR + wk8]) = wbh;
            *reinterpret_cast<uint4*>(&sWl[wn * BSTR + wk8]) = wbl;
            if (ch + 1 < NCHC) ldg_w(ch + 1);
        }

        // keep the pipeline full
        if (ch + 3 < NCHC) issue_chunk(ch + 3);
        else CP_COMMIT();      // empty group keeps wait_group counting valid

        __syncthreads();       // bf16 tiles ready

        // MMA: 2 k-steps of 16
        #pragma unroll
        for (int ks = 0; ks < 2; ks++) {
            uint32_t koff = (uint32_t)(ks * 16) * 2;
            uint32_t ah[4], al[4];
            ldsm_x4(ah[0], ah[1], ah[2], ah[3], aH + koff);
            ldsm_x4(al[0], al[1], al[2], al[3], aL + koff);
            #pragma unroll
            for (int pr = 0; pr < 2; pr++) {
                uint32_t poff = (uint32_t)(pr * 16 * BSTR) * 2 + koff;
                uint32_t bh[4], bl[4];
                ldsm_x4(bh[0], bh[1], bh[2], bh[3], bH + poff);
                ldsm_x4(bl[0], bl[1], bl[2], bl[3], bL + poff);
                mma_bf16(acc[2 * pr],     ah, bh[0], bh[1]);
                mma_bf16(acc[2 * pr],     ah, bl[0], bl[1]);
                mma_bf16(acc[2 * pr],     al, bh[0], bh[1]);
                mma_bf16(acc[2 * pr + 1], ah, bh[2], bh[3]);
                mma_bf16(acc[2 * pr + 1], ah, bl[2], bl[3]);
                mma_bf16(acc[2 * pr + 1], al, bh[2], bh[3]);
            }
        }
    }

    // epilogue: +bias, exp, negate b-block, store transposed [p][bt]
    const int g  = lid >> 2;
    const int tg = lid & 3;
    #pragma unroll
    for (int nt = 0; nt < 4; nt++) {
        int p0 = nt * 8 + tg * 2;
        #pragma unroll
        for (int dp = 0; dp < 2; dp++) {
            int p = p0 + dp;
            if (p < NP) {
                float bz = bias[p];
                float e0 = expf(acc[nt][dp] + bz);
                float e1 = expf(acc[nt][2 + dp] + bz);
                if (p >= NK && p < 2 * NK) { e0 = -e0; e1 = -e1; }
                g_par[p * BT + t0 + m0 + g]     = e0;
                g_par[p * BT + t0 + m0 + g + 8] = e1;
            }
        }
    }
}

// ---------------------------------------------------------------------------
// Kernel 2 (R10 verbatim, measured 9.3us): window + mix, scalar FFMA.
// ---------------------------------------------------------------------------
#define BPB    32
#define UCHUNK 32
#define SUBS   8
#define APT    (NA / SUBS)   // 10

__global__ __launch_bounds__(256) void k2_window(
    const float* __restrict__ charseq,
    float* __restrict__ out)
{
    __shared__ float spar[NP * BPB];
    __shared__ float sphi[BPB][UCHUNK + 1];
    __shared__ float scs[UCHUNK][NA];

    const int tid = threadIdx.x;
    const int bt0 = blockIdx.x * BPB;
    const int b   = bt0 >> 10;
    const float* cbase = charseq + (size_t)b * NU * NA;

    float4 csr[3];
    const float4* cb4 = reinterpret_cast<const float4*>(cbase);
    #pragma unroll
    for (int j = 0; j < 3; j++) {
        int idx = tid + 256 * j;
        if (idx < UCHUNK * (NA / 4)) csr[j] = cb4[idx];
    }
    float pr[4];
    #pragma unroll
    for (int j = 0; j < 4; j++) {
        int idx = tid + 256 * j;
        if (idx < NP * BPB) {
            int p = idx >> 5, bl = idx & 31;
            pr[j] = g_par[p * BT + bt0 + bl];
        }
    }
    float4* scs4 = reinterpret_cast<float4*>(&scs[0][0]);
    #pragma unroll
    for (int j = 0; j < 3; j++) {
        int idx = tid + 256 * j;
        if (idx < UCHUNK * (NA / 4)) scs4[idx] = csr[j];
    }
    #pragma unroll
    for (int j = 0; j < 4; j++) {
        int idx = tid + 256 * j;
        if (idx < NP * BPB) spar[idx] = pr[j];
    }
    __syncthreads();

    const int bl  = tid >> 3;
    const int sub = tid & 7;

    float a[NK], nb[NK], kk[NK];
    #pragma unroll
    for (int k = 0; k < NK; k++) {
        a[k]  = spar[k * BPB + bl];
        nb[k] = spar[(NK + k) * BPB + bl];
        kk[k] = spar[(2 * NK + k) * BPB + bl];
    }

    float cut = 1.f;
    #pragma unroll
    for (int k = 0; k < NK; k++)
        cut = fmaxf(cut, kk[k] + __fsqrt_rn(__fdividef(48.f, -nb[k])));
    const int ucut = min(NU, (int)cut + 1);

    #pragma unroll
    for (int r = 0; r < UCHUNK / 8; r++) {
        int u = sub + 8 * r;
        if (u < ucut) {
            float uf  = (float)u;
            float phi = 0.f;
            #pragma unroll
            for (int k = 0; k < NK; k++) {
                float d = kk[k] - uf;
                phi += a[k] * __expf(nb[k] * d * d);
            }
            sphi[bl][u] = phi;
        }
    }
    __syncthreads();

    float acc[APT];
    #pragma unroll
    for (int j = 0; j < APT; j++) acc[j] = 0.f;

    const int uend = min(ucut, UCHUNK);
    for (int u = 0; u < uend; u++) {
        float phi = sphi[bl][u];
        const float* r = &scs[u][sub * APT];
        #pragma unroll
        for (int j = 0; j < APT / 2; j++) {
            float2 cv = *reinterpret_cast<const float2*>(r + 2 * j);
            acc[2 * j + 0] = fmaf(phi, cv.x, acc[2 * j + 0]);
            acc[2 * j + 1] = fmaf(phi, cv.y, acc[2 * j + 1]);
        }
    }
    for (int u = UCHUNK; u < ucut; u++) {
        float uf  = (float)u;
        float phi = 0.f;
        #pragma unroll
        for (int k = 0; k < NK; k++) {
            float d = kk[k] - uf;
            phi += a[k] * __expf(nb[k] * d * d);
        }
        const float* r = cbase + (size_t)u * NA + sub * APT;
        #pragma unroll
        for (int j = 0; j < APT; j++)
            acc[j] = fmaf(phi, __ldg(r + j), acc[j]);
    }

    float2* op = reinterpret_cast<float2*>(out + (size_t)bt0 * NA +
                                           (size_t)bl * NA + sub * APT);
    #pragma unroll
    for (int j = 0; j < APT / 2; j++)
        op[j] = make_float2(acc[2 * j], acc[2 * j + 1]);
}

// ---------------------------------------------------------------------------
extern "C" void kernel_launch(void* const* d_in, const int* in_sizes, int n_in,
                              void* d_out, int out_size)
{
    const float* lstm = (const float*)d_in[0];   // [16,1024,512]
    const float* cs   = (const float*)d_in[1];   // [16,600,80]
    const float* W    = (const float*)d_in[2];   // [512,30]
    const float* bias = (const float*)d_in[3];   // [30]
    float* out = (float*)d_out;                  // [16,1024,80]

    (void)in_sizes; (void)n_in; (void)out_size;

    static int smem_set = 0;
    if (!smem_set) {
        cudaFuncSetAttribute(k1_hmma,
                             cudaFuncAttributeMaxDynamicSharedMemorySize,
                             K1_SMEM);
        smem_set = 1;
    }
    k0_wsplit<<<64, 256>>>(W);
    k1_hmma<<<BT / MROWS, K1T, K1_SMEM>>>(lstm, bias);
    k2_window<<<BT / BPB, 256>>>(cs, out);
}

// round 17
// speedup vs baseline: 1.0638x; 1.0638x over previous
#include <cuda_runtime.h>
#include <cuda_bf16.h>
#include <cstdint>

// Problem constants (fixed shapes)
#define BT    16384      // B*T
#define HID   512
#define NP    30
#define NU    600
#define NA    80
#define NK    10

// Scratch: transposed exp'ed params [p][bt].
__device__ float g_par[NP * BT];
// Pre-split W, transposed n-major: [n][k], n padded 30->32 with zeros.
__device__ __nv_bfloat16 g_wh[32 * HID];
__device__ __nv_bfloat16 g_wl[32 * HID];

__device__ __forceinline__ uint32_t smem_u32(const void* p) {
    return (uint32_t)__cvta_generic_to_shared(p);
}
__device__ __forceinline__ void ldsm_x4(uint32_t& r0, uint32_t& r1,
                                        uint32_t& r2, uint32_t& r3, uint32_t addr) {
    asm volatile("ldmatrix.sync.aligned.m8n8.x4.shared.b16 {%0,%1,%2,%3}, [%4];"
                 : "=r"(r0), "=r"(r1), "=r"(r2), "=r"(r3) : "r"(addr));
}
__device__ __forceinline__ void mma_bf16(float* c, const uint32_t* a,
                                         uint32_t b0, uint32_t b1) {
    asm volatile(
        "mma.sync.aligned.m16n8k16.row.col.f32.bf16.bf16.f32 "
        "{%0,%1,%2,%3}, {%4,%5,%6,%7}, {%8,%9}, {%0,%1,%2,%3};"
        : "+f"(c[0]), "+f"(c[1]), "+f"(c[2]), "+f"(c[3])
        : "r"(a[0]), "r"(a[1]), "r"(a[2]), "r"(a[3]), "r"(b0), "r"(b1));
}

// ---------------------------------------------------------------------------
// Kernel 0 (ramp sponge + W split): first launch absorbs the DVFS clock ramp;
// splits W into bf16 hi/lo transposed [32][512].
// ---------------------------------------------------------------------------
__global__ __launch_bounds__(256) void k0_wsplit(const float* __restrict__ W)
{
    int idx = blockIdx.x * 256 + threadIdx.x;   // 0..16383
    int n = idx >> 9, k = idx & 511;
    float f = (n < NP) ? W[(size_t)k * NP + n] : 0.f;
    __nv_bfloat16 hi = __float2bfloat16(f);
    __nv_bfloat16 lo = __float2bfloat16(f - __bfloat162float(hi));
    g_wh[idx] = hi;
    g_wl[idx] = lo;
}

// ---------------------------------------------------------------------------
// Kernel 1 (R10 structure, 8 warps): params = lstm @ W + bias -> exp -> g_par.
// 256 CTAs x 64 t; 256 threads. Warp w = (mt = w>>1) m16-tile x (nh = w&1)
// n16-half. K=512 in 8 chunks of 64; A register-prefetched; W from pre-split
// global (pure LDG.128 -> STS.128). 3-term bf16 split (Ah*Wh+Ah*Wl+Al*Wh).
// Smem stride 72 bf16 (144B): conflict-free ldmatrix (verified R9/R10).
// ---------------------------------------------------------------------------
#define K1T    256
#define MROWS  64
#define CHUNK  64
#define NCH    (HID / CHUNK)   // 8
#define ASTR   72              // smem row stride in bf16 elems (144 B)

__global__ __launch_bounds__(K1T) void k1_hmma(
    const float* __restrict__ lstm,
    const float* __restrict__ bias)
{
    __shared__ __align__(16) __nv_bfloat16 sAh[MROWS * ASTR];  // 9 KB
    __shared__ __align__(16) __nv_bfloat16 sAl[MROWS * ASTR];  // 9 KB
    __shared__ __align__(16) __nv_bfloat16 sBh[32 * ASTR];     // 4.5 KB
    __shared__ __align__(16) __nv_bfloat16 sBl[32 * ASTR];     // 4.5 KB

    const int tid = threadIdx.x;
    const int wid = tid >> 5;
    const int lid = tid & 31;
    const int t0  = blockIdx.x * MROWS;
    const int m0  = (wid >> 1) * 16;
    const int nh  = (wid & 1) * 16;

    float acc[2][4];
    #pragma unroll
    for (int n = 0; n < 2; n++)
        #pragma unroll
        for (int j = 0; j < 4; j++) acc[n][j] = 0.f;

    // ldmatrix lane addresses (fixed per thread)
    const int a_row = m0 + (lid & 15);
    const int a_c8  = (lid & 16) ? 8 : 0;
    const uint32_t aBh = smem_u32(sAh) + (uint32_t)(a_row * ASTR + a_c8) * 2;
    const uint32_t aBl = smem_u32(sAl) + (uint32_t)(a_row * ASTR + a_c8) * 2;
    const int b_k8  = (lid & 8) ? 8 : 0;
    const int b_n   = nh + (lid & 7) + ((lid & 16) ? 8 : 0);
    const uint32_t bBh = smem_u32(sBh) + (uint32_t)(b_n * ASTR + b_k8) * 2;
    const uint32_t bBl = smem_u32(sBl) + (uint32_t)(b_n * ASTR + b_k8) * 2;

    // W staging: 32n x 64k bf16 per split = 256 uint4; 1 per thread per split
    const int wn = tid >> 3, wk8 = (tid & 7) * 8;

    // ---- prologue: prefetch chunk 0
    float4 va[4];
    uint4  wbh, wbl;
    #pragma unroll
    for (int j = 0; j < 4; j++) {
        int idx = tid + K1T * j;               // 0..1023
        int row = idx >> 4, c4 = idx & 15;
        va[j] = *reinterpret_cast<const float4*>(
            lstm + (size_t)(t0 + row) * HID + c4 * 4);
    }
    wbh = *reinterpret_cast<const uint4*>(&g_wh[wn * HID + wk8]);
    wbl = *reinterpret_cast<const uint4*>(&g_wl[wn * HID + wk8]);

    #pragma unroll 1
    for (int ch = 0; ch < NCH; ch++) {
        __syncthreads();    // previous compute done reading smem
        // ---- STS staged A (paired bf16x2 converts) + W (raw copy)
        #pragma unroll
        for (int j = 0; j < 4; j++) {
            int idx = tid + K1T * j;
            int row = idx >> 4, c4 = idx & 15;
            float4 v = va[j];
            __nv_bfloat162 h01 = __float22bfloat162_rn(make_float2(v.x, v.y));
            __nv_bfloat162 h23 = __float22bfloat162_rn(make_float2(v.z, v.w));
            float2 f01 = __bfloat1622float2(h01);
            float2 f23 = __bfloat1622float2(h23);
            __nv_bfloat162 l01 = __float22bfloat162_rn(
                make_float2(v.x - f01.x, v.y - f01.y));
            __nv_bfloat162 l23 = __float22bfloat162_rn(
                make_float2(v.z - f23.x, v.w - f23.y));
            *reinterpret_cast<uint2*>(&sAh[row * ASTR + c4 * 4]) =
                make_uint2(*reinterpret_cast<uint32_t*>(&h01),
                           *reinterpret_cast<uint32_t*>(&h23));
            *reinterpret_cast<uint2*>(&sAl[row * ASTR + c4 * 4]) =
                make_uint2(*reinterpret_cast<uint32_t*>(&l01),
                           *reinterpret_cast<uint32_t*>(&l23));
        }
        *reinterpret_cast<uint4*>(&sBh[wn * ASTR + wk8]) = wbh;
        *reinterpret_cast<uint4*>(&sBl[wn * ASTR + wk8]) = wbl;
        __syncthreads();

        // ---- prefetch next chunk (overlaps MMA compute below)
        if (ch + 1 < NCH) {
            int k0 = (ch + 1) * CHUNK;
            #pragma unroll
            for (int j = 0; j < 4; j++) {
                int idx = tid + K1T * j;
                int row = idx >> 4, c4 = idx & 15;
                va[j] = *reinterpret_cast<const float4*>(
                    lstm + (size_t)(t0 + row) * HID + k0 + c4 * 4);
            }
            wbh = *reinterpret_cast<const uint4*>(&g_wh[wn * HID + k0 + wk8]);
            wbl = *reinterpret_cast<const uint4*>(&g_wl[wn * HID + k0 + wk8]);
        }

        // ---- compute: 4 k-steps of 16
        #pragma unroll
        for (int ks = 0; ks < 4; ks++) {
            uint32_t koff = (uint32_t)(ks * 16) * 2;   // bytes
            uint32_t ah[4], al[4], bh[4], bl[4];
            ldsm_x4(ah[0], ah[1], ah[2], ah[3], aBh + koff);
            ldsm_x4(al[0], al[1], al[2], al[3], aBl + koff);
            ldsm_x4(bh[0], bh[1], bh[2], bh[3], bBh + koff);
            ldsm_x4(bl[0], bl[1], bl[2], bl[3], bBl + koff);
            mma_bf16(acc[0], ah, bh[0], bh[1]);
            mma_bf16(acc[0], ah, bl[0], bl[1]);
            mma_bf16(acc[0], al, bh[0], bh[1]);
            mma_bf16(acc[1], ah, bh[2], bh[3]);
            mma_bf16(acc[1], ah, bl[2], bl[3]);
            mma_bf16(acc[1], al, bh[2], bh[3]);
        }
    }

    // ---- epilogue: +bias, exp, negate b-block, store transposed [p][bt]
    const int g  = lid >> 2;
    const int tg = lid & 3;
    #pragma unroll
    for (int nt = 0; nt < 2; nt++) {
        int p0 = nh + nt * 8 + tg * 2;
        #pragma unroll
        for (int dp = 0; dp < 2; dp++) {
            int p = p0 + dp;
            if (p < NP) {
                float bz = bias[p];
                float e0 = expf(acc[nt][dp] + bz);       // row m0+g
                float e1 = expf(acc[nt][2 + dp] + bz);   // row m0+g+8
                if (p >= NK && p < 2 * NK) { e0 = -e0; e1 = -e1; }
                g_par[p * BT + t0 + m0 + g]     = e0;
                g_par[p * BT + t0 + m0 + g + 8] = e1;
            }
        }
    }
}

// ---------------------------------------------------------------------------
// Kernel 2 (R10 verbatim, measured 9.3us): window + mix, scalar FFMA.
// One batched load (charseq rows [0,32) + params), sync, phi->smem, sync,
// LDS+FFMA. Analytic ucut <= kappa_max + sqrt(48/b_min) ~ 27 < 32; u>=32
// tail reads global (correct fallback, analytically never taken).
// ---------------------------------------------------------------------------
#define BPB    32
#define UCHUNK 32
#define SUBS   8
#define APT    (NA / SUBS)   // 10

__global__ __launch_bounds__(256) void k2_window(
    const float* __restrict__ charseq,
    float* __restrict__ out)
{
    __shared__ float spar[NP * BPB];
    __shared__ float sphi[BPB][UCHUNK + 1];
    __shared__ float scs[UCHUNK][NA];

    const int tid = threadIdx.x;
    const int bt0 = blockIdx.x * BPB;
    const int b   = bt0 >> 10;
    const float* cbase = charseq + (size_t)b * NU * NA;

    float4 csr[3];
    const float4* cb4 = reinterpret_cast<const float4*>(cbase);
    #pragma unroll
    for (int j = 0; j < 3; j++) {
        int idx = tid + 256 * j;
        if (idx < UCHUNK * (NA / 4)) csr[j] = cb4[idx];
    }
    float pr[4];
    #pragma unroll
    for (int j = 0; j < 4; j++) {
        int idx = tid + 256 * j;
        if (idx < NP * BPB) {
            int p = idx >> 5, bl = idx & 31;
            pr[j] = g_par[p * BT + bt0 + bl];
        }
    }
    float4* scs4 = reinterpret_cast<float4*>(&scs[0][0]);
    #pragma unroll
    for (int j = 0; j < 3; j++) {
        int idx = tid + 256 * j;
        if (idx < UCHUNK * (NA / 4)) scs4[idx] = csr[j];
    }
    #pragma unroll
    for (int j = 0; j < 4; j++) {
        int idx = tid + 256 * j;
        if (idx < NP * BPB) spar[idx] = pr[j];
    }
    __syncthreads();

    const int bl  = tid >> 3;
    const int sub = tid & 7;

    float a[NK], nb[NK], kk[NK];
    #pragma unroll
    for (int k = 0; k < NK; k++) {
        a[k]  = spar[k * BPB + bl];
        nb[k] = spar[(NK + k) * BPB + bl];
        kk[k] = spar[(2 * NK + k) * BPB + bl];
    }

    float cut = 1.f;
    #pragma unroll
    for (int k = 0; k < NK; k++)
        cut = fmaxf(cut, kk[k] + __fsqrt_rn(__fdividef(48.f, -nb[k])));
    const int ucut = min(NU, (int)cut + 1);

    #pragma unroll
    for (int r = 0; r < UCHUNK / 8; r++) {
        int u = sub + 8 * r;
        if (u < ucut) {
            float uf  = (float)u;
            float phi = 0.f;
            #pragma unroll
            for (int k = 0; k < NK; k++) {
                float d = kk[k] - uf;
                phi += a[k] * __expf(nb[k] * d * d);
            }
            sphi[bl][u] = phi;
        }
    }
    __syncthreads();

    float acc[APT];
    #pragma unroll
    for (int j = 0; j < APT; j++) acc[j] = 0.f;

    const int uend = min(ucut, UCHUNK);
    for (int u = 0; u < uend; u++) {
        float phi = sphi[bl][u];
        const float* r = &scs[u][sub * APT];
        #pragma unroll
        for (int j = 0; j < APT / 2; j++) {
            float2 cv = *reinterpret_cast<const float2*>(r + 2 * j);
            acc[2 * j + 0] = fmaf(phi, cv.x, acc[2 * j + 0]);
            acc[2 * j + 1] = fmaf(phi, cv.y, acc[2 * j + 1]);
        }
    }
    for (int u = UCHUNK; u < ucut; u++) {
        float uf  = (float)u;
        float phi = 0.f;
        #pragma unroll
        for (int k = 0; k < NK; k++) {
            float d = kk[k] - uf;
            phi += a[k] * __expf(nb[k] * d * d);
        }
        const float* r = cbase + (size_t)u * NA + sub * APT;
        #pragma unroll
        for (int j = 0; j < APT; j++)
            acc[j] = fmaf(phi, __ldg(r + j), acc[j]);
    }

    float2* op = reinterpret_cast<float2*>(out + (size_t)(bt0 + bl) * NA + sub * APT);
    #pragma unroll
    for (int j = 0; j < APT / 2; j++)
        op[j] = make_float2(acc[2 * j], acc[2 * j + 1]);
}

// ---------------------------------------------------------------------------
extern "C" void kernel_launch(void* const* d_in, const int* in_sizes, int n_in,
                              void* d_out, int out_size)
{
    const float* lstm = (const float*)d_in[0];   // [16,1024,512]
    const float* cs   = (const float*)d_in[1];   // [16,600,80]
    const float* W    = (const float*)d_in[2];   // [512,30]
    const float* bias = (const float*)d_in[3];   // [30]
    float* out = (float*)d_out;                  // [16,1024,80]

    (void)in_sizes; (void)n_in; (void)out_size;

    k0_wsplit<<<64, 256>>>(W);
    k1_hmma<<<BT / MROWS, K1T>>>(lstm, bias);
    k2_window<<<BT / BPB, 256>>>(cs, out);
}